// round 15
// baseline (speedup 1.0000x reference)
#include <cuda_runtime.h>
#include <cuda_fp16.h>
#include <cstdint>
#include <math.h>

// ---------------- scratch (static __device__, no allocation) ----------------
__device__ float g_part[4*4*3*4096];     // attention partials [b][ks][3][q]
__device__ float g_warp[4*2*4096];       // coarse_warp [b][2][p]
__device__ float g_bufA[4194304];        // conv output (fp32)
__device__ float g_up[4*3*16384];        // upsampled coarse matches
__device__ float g_mean[256];
__device__ float g_istd[256];
__device__ float g_bnpart[16384];        // per-block BN partials: [2][C][NS]
__device__ uint32_t g_whi[1124352];      // packed fp16-hi weight planes (half2)
__device__ uint32_t g_wlo[1124352];      // packed fp16-lo weight planes
__device__ __align__(16) uint32_t g_aHi[2097152];  // activation hi planes
__device__ __align__(16) uint32_t g_aLo[2097152];  // activation lo planes

// ---------------- cp.async helpers ----------------
__device__ __forceinline__ uint32_t smem_u32(const void* p) {
    return (uint32_t)__cvta_generic_to_shared(p);
}
__device__ __forceinline__ void cp_async16(uint32_t dst, const void* src, int srcsz) {
    asm volatile("cp.async.ca.shared.global [%0], [%1], 16, %2;\n"
                 :: "r"(dst), "l"(src), "r"(srcsz));
}
__device__ __forceinline__ void cp_commit() {
    asm volatile("cp.async.commit_group;\n");
}
__device__ __forceinline__ void cp_wait1() {
    asm volatile("cp.async.wait_group 1;\n");
}
__device__ __forceinline__ void cp_wait0() {
    asm volatile("cp.async.wait_group 0;\n");
}

// ---------------- fp16 mma / ldmatrix / split helpers ----------------
__device__ __forceinline__ void mma_f16(float* c, const uint32_t* a, const uint32_t* b) {
    asm volatile("mma.sync.aligned.m16n8k16.row.col.f32.f16.f16.f32 "
        "{%0,%1,%2,%3}, {%4,%5,%6,%7}, {%8,%9}, {%0,%1,%2,%3};"
        : "+f"(c[0]), "+f"(c[1]), "+f"(c[2]), "+f"(c[3])
        : "r"(a[0]), "r"(a[1]), "r"(a[2]), "r"(a[3]), "r"(b[0]), "r"(b[1]));
}
__device__ __forceinline__ void ldsm_x4(uint32_t& r0, uint32_t& r1, uint32_t& r2,
                                        uint32_t& r3, uint32_t addr) {
    asm volatile("ldmatrix.sync.aligned.m8n8.x4.shared.b16 {%0,%1,%2,%3}, [%4];"
        : "=r"(r0), "=r"(r1), "=r"(r2), "=r"(r3) : "r"(addr));
}
__device__ __forceinline__ void split2(float f0, float f1, uint32_t& hi, uint32_t& lo) {
    __half h0 = __float2half_rn(f0), h1 = __float2half_rn(f1);
    __half2 hh = __halves2half2(h0, h1);
    __half2 ll = __halves2half2(__float2half_rn(f0 - __half2float(h0)),
                                __float2half_rn(f1 - __half2float(h1)));
    hi = *(uint32_t*)&hh;
    lo = *(uint32_t*)&ll;
}

// ---------------- weight pre-split into packed chunk planes ----------------
__global__ void wsplit16(const float* __restrict__ w, uint32_t* __restrict__ hi,
                         uint32_t* __restrict__ lo, int cinReal, int nch, int n)
{
    int idx = blockIdx.x*256 + threadIdx.x;
    if (idx >= n) return;
    int p  = idx & 7;
    int r1 = idx >> 3;
    int o  = r1 & 31;
    int r2 = r1 >> 5;
    int k  = r2 % 9;
    int r3 = r2 / 9;
    int ch = r3 % nch;
    int ob = r3 / nch;
    int oc = ob*32 + o;
    int ic0 = ch*16 + 2*p;
    float f0 = (ic0   < cinReal) ? w[((size_t)oc*cinReal + ic0  )*9 + k] : 0.f;
    float f1 = (ic0+1 < cinReal) ? w[((size_t)oc*cinReal + ic0+1)*9 + k] : 0.f;
    split2(f0, f1, hi[idx], lo[idx]);
}

// ---------------- fused correlation-softmax-expectation ----------------
__global__ void __launch_bounds__(256) attn_kernel(const float* __restrict__ f0,
                                                   const float* __restrict__ f1)
{
    __shared__ __align__(16) float sK[64][64];
    const int qb = blockIdx.x, ks = blockIdx.y, b = blockIdx.z;
    const int q = qb*256 + threadIdx.x;
    const float* f0b = f0 + (size_t)b*262144;
    const float* f1b = f1 + (size_t)b*262144;
    float qv[64];
#pragma unroll
    for (int c=0;c<64;c++) qv[c] = f0b[c*4096 + q];
    float sE=0.f, sX=0.f, sY=0.f;
    const int kbase = ks*1024;
    for (int t=0; t<1024; t+=64) {
        __syncthreads();
        const int k0 = kbase + t;
        for (int idx=threadIdx.x; idx<4096; idx+=256) {
            int c = idx>>6, kk = idx&63;
            sK[c][kk] = f1b[c*4096 + k0 + kk];
        }
        __syncthreads();
        const float gyv = (float)((k0>>6)*2 + 1)*0.015625f - 1.0f;
        for (int kk=0; kk<64; kk+=4) {
            float d0=0.f,d1=0.f,d2=0.f,d3=0.f;
#pragma unroll
            for (int c=0;c<64;c++) {
                float4 kv = *(const float4*)&sK[c][kk];
                d0 = fmaf(qv[c], kv.x, d0);
                d1 = fmaf(qv[c], kv.y, d1);
                d2 = fmaf(qv[c], kv.z, d2);
                d3 = fmaf(qv[c], kv.w, d3);
            }
            float e0 = __expf(d0*0.125f);
            float e1 = __expf(d1*0.125f);
            float e2 = __expf(d2*0.125f);
            float e3 = __expf(d3*0.125f);
            float gx0 = (float)((((k0+kk)&63)*2)+1)*0.015625f - 1.0f;
            float es = e0+e1+e2+e3;
            sE += es;
            sY = fmaf(es, gyv, sY);
            sX += e0*gx0 + e1*(gx0+0.03125f) + e2*(gx0+0.0625f) + e3*(gx0+0.09375f);
        }
    }
    size_t base = ((size_t)(b*4+ks)*3)*4096 + q;
    g_part[base        ] = sE;
    g_part[base +  4096] = sX;
    g_part[base +  8192] = sY;
}

__global__ void attn_combine()
{
    int i = blockIdx.x*256 + threadIdx.x;      // 16384
    if (i >= 16384) return;
    int b = i>>12, q = i&4095;
    float sE=0.f, sX=0.f, sY=0.f;
    for (int ks=0; ks<4; ks++) {
        size_t base = ((size_t)(b*4+ks)*3)*4096 + q;
        sE += g_part[base];
        sX += g_part[base+4096];
        sY += g_part[base+8192];
    }
    float inv = 1.0f/sE;
    g_warp[(size_t)(b*2  )*4096 + q] = sX*inv;
    g_warp[(size_t)(b*2+1)*4096 + q] = sY*inv;
}

// ---------------- coarse concat + grid_sample -> split planes (nch=9) ------
__global__ void pack_coarse_split(const float* __restrict__ f0c,
                                  const float* __restrict__ f1c)
{
    int i = blockIdx.x*256 + threadIdx.x;      // 16384
    if (i >= 16384) return;
    int b = i>>12, p = i&4095;
    int ch = blockIdx.y;                       // 0..8
    float wx = g_warp[(size_t)(b*2  )*4096 + p];
    float wy = g_warp[(size_t)(b*2+1)*4096 + p];

    float vals[16];
    if (ch < 4) {
        const float* f0b = f0c + (size_t)b*262144;
#pragma unroll
        for (int j=0;j<16;j++) vals[j] = f0b[(size_t)(ch*16+j)*4096 + p];
    } else if (ch < 8) {
        float fx = (wx + 1.f)*32.f - 0.5f;
        float fy = (wy + 1.f)*32.f - 0.5f;
        float flx = floorf(fx), fly = floorf(fy);
        float ax = fx - flx, ay = fy - fly;
        int xi = (int)flx, yi = (int)fly;
        float vx0 = ((unsigned)xi     < 64u) ? 1.f : 0.f;
        float vx1 = ((unsigned)(xi+1) < 64u) ? 1.f : 0.f;
        float vy0 = ((unsigned)yi     < 64u) ? 1.f : 0.f;
        float vy1 = ((unsigned)(yi+1) < 64u) ? 1.f : 0.f;
        int cx0 = min(max(xi,0),63),   cx1 = min(max(xi+1,0),63);
        int cy0 = min(max(yi,0),63),   cy1 = min(max(yi+1,0),63);
        float w00 = (1.f-ax)*(1.f-ay)*vx0*vy0;
        float w01 = ax*(1.f-ay)*vx1*vy0;
        float w10 = (1.f-ax)*ay*vx0*vy1;
        float w11 = ax*ay*vx1*vy1;
        int i00 = cy0*64+cx0, i01 = cy0*64+cx1, i10 = cy1*64+cx0, i11 = cy1*64+cx1;
        const float* f1b = f1c + (size_t)b*262144;
#pragma unroll
        for (int j=0;j<16;j++) {
            const float* fc = f1b + (size_t)((ch-4)*16+j)*4096;
            vals[j] = w00*fc[i00] + w01*fc[i01] + w10*fc[i10] + w11*fc[i11];
        }
    } else {
#pragma unroll
        for (int j=0;j<16;j++) vals[j] = 0.f;
        vals[0] = wx; vals[1] = wy;
    }

    uint32_t h[8], l[8];
#pragma unroll
    for (int j=0;j<8;j++) split2(vals[2*j], vals[2*j+1], h[j], l[j]);
    size_t off = (((size_t)(b*9 + ch)) << 12) + p;
    uint4* H4 = (uint4*)g_aHi;
    uint4* L4 = (uint4*)g_aLo;
    H4[off*2]   = make_uint4(h[0],h[1],h[2],h[3]);
    H4[off*2+1] = make_uint4(h[4],h[5],h[6],h[7]);
    L4[off*2]   = make_uint4(l[0],l[1],l[2],l[3]);
    L4[off*2+1] = make_uint4(l[4],l[5],l[6],l[7]);
}

// ---------------- fine concat + grid_sample -> split planes (nch=4) --------
__global__ void pack_fine_split(const float* __restrict__ f0f,
                                const float* __restrict__ f1f)
{
    int i = blockIdx.x*256 + threadIdx.x;      // 65536
    if (i >= 65536) return;
    int b = i>>14, p = i&16383;
    int ch = blockIdx.y;                       // 0..3
    float wx = g_up[(size_t)(b*3  )*16384 + p];
    float wy = g_up[(size_t)(b*3+1)*16384 + p];

    float w00=0,w01=0,w10=0,w11=0;
    int i00=0,i01=0,i10=0,i11=0;
    if (ch == 1 || ch == 2) {
        float fx = (wx + 1.f)*64.f - 0.5f;
        float fy = (wy + 1.f)*64.f - 0.5f;
        float flx = floorf(fx), fly = floorf(fy);
        float ax = fx - flx, ay = fy - fly;
        int xi = (int)flx, yi = (int)fly;
        float vx0 = ((unsigned)xi     < 128u) ? 1.f : 0.f;
        float vx1 = ((unsigned)(xi+1) < 128u) ? 1.f : 0.f;
        float vy0 = ((unsigned)yi     < 128u) ? 1.f : 0.f;
        float vy1 = ((unsigned)(yi+1) < 128u) ? 1.f : 0.f;
        int cx0 = min(max(xi,0),127),  cx1 = min(max(xi+1,0),127);
        int cy0 = min(max(yi,0),127),  cy1 = min(max(yi+1,0),127);
        w00 = (1.f-ax)*(1.f-ay)*vx0*vy0;
        w01 = ax*(1.f-ay)*vx1*vy0;
        w10 = (1.f-ax)*ay*vx0*vy1;
        w11 = ax*ay*vx1*vy1;
        i00 = cy0*128+cx0; i01 = cy0*128+cx1; i10 = cy1*128+cx0; i11 = cy1*128+cx1;
    }
    const float* f0b = f0f + (size_t)b*24*16384;
    const float* f1b = f1f + (size_t)b*24*16384;

    float vals[16];
#pragma unroll
    for (int j=0;j<16;j++) {
        int c = ch*16 + j;
        float v;
        if (c < 24) {
            v = f0b[(size_t)c*16384 + p];
        } else if (c < 48) {
            const float* fc = f1b + (size_t)(c-24)*16384;
            v = w00*fc[i00] + w01*fc[i01] + w10*fc[i10] + w11*fc[i11];
        } else if (c == 48) v = wx;
        else if (c == 49) v = wy;
        else v = 0.f;
        vals[j] = v;
    }

    uint32_t h[8], l[8];
#pragma unroll
    for (int j=0;j<8;j++) split2(vals[2*j], vals[2*j+1], h[j], l[j]);
    size_t off = (((size_t)(b*4 + ch)) << 14) + p;
    uint4* H4 = (uint4*)g_aHi;
    uint4* L4 = (uint4*)g_aLo;
    H4[off*2]   = make_uint4(h[0],h[1],h[2],h[3]);
    H4[off*2+1] = make_uint4(h[4],h[5],h[6],h[7]);
    L4[off*2]   = make_uint4(l[0],l[1],l[2],l[3]);
    L4[off*2+1] = make_uint4(l[4],l[5],l[6],l[7]);
}

// ---------------- fp16 m16n8k16 tensor-core 3x3 conv ------------------------
// Block: 32 oc x (16 rows x 32 cols). 8 warps; warp w owns rows 2w,2w+1.
// Fragments loaded via ldmatrix.x4 (4 regs/instr). XOR 16B swizzle keeps all
// ldmatrix phases conflict-free. Fused per-channel BN partial sums in epilogue.
template<int NCH>
__global__ void __launch_bounds__(256,2) conv16(
    const uint32_t* __restrict__ aHi, const uint32_t* __restrict__ aLo,
    const uint32_t* __restrict__ wHi, const uint32_t* __restrict__ wLo,
    float* __restrict__ out, int cout, int H, int W, int NS)
{
    __shared__ __align__(16) uint32_t sInH[2][18][34][8];
    __shared__ __align__(16) uint32_t sInL[2][18][34][8];
    __shared__ __align__(16) uint32_t sWH[2][9][32][8];
    __shared__ __align__(16) uint32_t sWL[2][9][32][8];
    __shared__ float sRed[8][32][2];
    const int HW = H*W;
    const int tilesX = W >> 5;
    const int tx = blockIdx.x % tilesX;
    const int ty = blockIdx.x / tilesX;
    const int ob = blockIdx.y;
    const int ocb = ob << 5;
    const int b = blockIdx.z;
    const int tid = threadIdx.x;
    const int lane = tid & 31;
    const int wid = tid >> 5;
    const int g = lane >> 2;
    const int t = lane & 3;
    const int x0 = tx << 5, y0 = ty << 4;

    auto stage = [&](int buf, int ch) {
        const size_t inBase = ((size_t)(b*NCH + ch))*HW;
        for (int idx=tid; idx<2448; idx+=256) {
            int pl = idx & 1;
            int h  = (idx>>1)&1;
            int e  = idx>>2;            // 0..611
            int x  = e % 34;
            int r  = e / 34;
            int yy = y0-1+r, xx = x0-1+x;
            bool ok = ((unsigned)yy < (unsigned)H) && ((unsigned)xx < (unsigned)W);
            int yc = min(max(yy,0),H-1), xc = min(max(xx,0),W-1);
            const uint32_t* src = (pl ? aLo : aHi) + (inBase + yc*W + xc)*8 + h*4;
            int ph = (h ^ ((x>>2)&1)) << 2;
            uint32_t dst = smem_u32(pl ? &sInL[buf][r][x][ph] : &sInH[buf][r][x][ph]);
            cp_async16(dst, src, ok ? 16 : 0);
        }
        const size_t wBase = ((size_t)(ob*NCH + ch))*2304;
        for (int idx=tid; idx<1152; idx+=256) {
            int pl = idx & 1;
            int h  = (idx>>1)&1;
            int e  = idx>>2;            // 0..287
            int o  = e & 31;
            int k  = e >> 5;
            const uint32_t* src = (pl ? wLo : wHi) + wBase + (size_t)(k*32 + o)*8 + h*4;
            int ph = (h ^ ((o>>2)&1)) << 2;
            uint32_t dst = smem_u32(pl ? &sWL[buf][k][o][ph] : &sWH[buf][k][o][ph]);
            cp_async16(dst, src, 16);
        }
        cp_commit();
    };

    // per-lane ldmatrix offsets (word units)
    const int j  = lane >> 3;
    const int lr = lane & 7;
    const int oB0 = 8*(j>>1) + lr;           // n-tiles {0,1}
    const int oB2 = oB0 + 16;                // n-tiles {2,3}
    const int hB  = j & 1;
    const int offB0 = oB0*8 + ((hB ^ ((oB0>>2)&1))<<2);
    const int offB2 = oB2*8 + ((hB ^ ((oB2>>2)&1))<<2);
    const int pixB = 8*(j&1) + lr;
    const int khalf = j >> 1;
    int offA[2][3];
#pragma unroll
    for (int m=0;m<2;m++)
#pragma unroll
        for (int kw=0;kw<3;kw++) {
            int px = pixB + 16*m + kw;
            offA[m][kw] = px*8 + ((khalf ^ ((px>>2)&1))<<2);
        }

    float c[2][2][4][4];
#pragma unroll
    for (int rr=0;rr<2;rr++)
#pragma unroll
        for (int m=0;m<2;m++)
#pragma unroll
            for (int n=0;n<4;n++)
#pragma unroll
                for (int e=0;e<4;e++) c[rr][m][n][e] = 0.f;

    stage(0, 0);

    for (int ci=0; ci<NCH; ci++) {
        if (ci+1 < NCH) {
            stage((ci+1)&1, ci+1);
            cp_wait1();
        } else {
            cp_wait0();
        }
        __syncthreads();
        const int buf = ci & 1;
#pragma unroll
        for (int kh=0;kh<3;kh++) {
#pragma unroll
            for (int kw=0;kw<3;kw++) {
                const int kidx = kh*3+kw;
                uint32_t bhB = smem_u32(&sWH[buf][kidx][0][0]);
                uint32_t blB = smem_u32(&sWL[buf][kidx][0][0]);
                uint32_t BH[4][2], BL[4][2];
                ldsm_x4(BH[0][0], BH[0][1], BH[1][0], BH[1][1], bhB + offB0*4);
                ldsm_x4(BH[2][0], BH[2][1], BH[3][0], BH[3][1], bhB + offB2*4);
                ldsm_x4(BL[0][0], BL[0][1], BL[1][0], BL[1][1], blB + offB0*4);
                ldsm_x4(BL[2][0], BL[2][1], BL[3][0], BL[3][1], blB + offB2*4);
#pragma unroll
                for (int rr=0;rr<2;rr++) {
                    int r = 2*wid + rr + kh;
                    uint32_t rhB = smem_u32(&sInH[buf][r][0][0]);
                    uint32_t rlB = smem_u32(&sInL[buf][r][0][0]);
#pragma unroll
                    for (int m=0;m<2;m++) {
                        uint32_t AH[4], AL[4];
                        ldsm_x4(AH[0], AH[1], AH[2], AH[3], rhB + offA[m][kw]*4);
                        ldsm_x4(AL[0], AL[1], AL[2], AL[3], rlB + offA[m][kw]*4);
#pragma unroll
                        for (int n=0;n<4;n++) {
                            mma_f16(c[rr][m][n], AH, BH[n]);
                            mma_f16(c[rr][m][n], AH, BL[n]);
                            mma_f16(c[rr][m][n], AL, BH[n]);
                        }
                    }
                }
            }
        }
        __syncthreads();
    }

    // store results
#pragma unroll
    for (int rr=0;rr<2;rr++) {
        const int oy = y0 + 2*wid + rr;
#pragma unroll
        for (int m=0;m<2;m++) {
#pragma unroll
            for (int n=0;n<4;n++) {
                int oc = ocb + 8*n + 2*t;
                float* p0 = out + ((size_t)b*cout + oc)*HW + oy*W + x0 + 16*m + g;
                p0[0] = c[rr][m][n][0];
                p0[8] = c[rr][m][n][2];
                float* p1 = p0 + HW;
                p1[0] = c[rr][m][n][1];
                p1[8] = c[rr][m][n][3];
            }
        }
    }

    // fused BN partial sums (deterministic per-block slot)
    {
        float sv[4][2], qv[4][2];
#pragma unroll
        for (int n=0;n<4;n++)
#pragma unroll
            for (int e=0;e<2;e++) {
                float a = 0.f, b2 = 0.f;
#pragma unroll
                for (int rr=0;rr<2;rr++)
#pragma unroll
                    for (int m=0;m<2;m++) {
                        float v0 = c[rr][m][n][e];
                        float v1 = c[rr][m][n][e+2];
                        a  += v0 + v1;
                        b2 += v0*v0 + v1*v1;
                    }
                sv[n][e] = a; qv[n][e] = b2;
            }
#pragma unroll
        for (int mask=4; mask<32; mask<<=1)
#pragma unroll
            for (int n=0;n<4;n++)
#pragma unroll
                for (int e=0;e<2;e++) {
                    sv[n][e] += __shfl_xor_sync(0xffffffffu, sv[n][e], mask);
                    qv[n][e] += __shfl_xor_sync(0xffffffffu, qv[n][e], mask);
                }
        if (lane < 4) {
#pragma unroll
            for (int n=0;n<4;n++)
#pragma unroll
                for (int e=0;e<2;e++) {
                    sRed[wid][n*8 + lane*2 + e][0] = sv[n][e];
                    sRed[wid][n*8 + lane*2 + e][1] = qv[n][e];
                }
        }
        __syncthreads();
        if (tid < 64) {
            int cl = tid & 31, which = tid >> 5;
            float v = 0.f;
#pragma unroll
            for (int w=0;w<8;w++) v += sRed[w][cl][which];
            int slot = blockIdx.x + gridDim.x*blockIdx.z;
            g_bnpart[which*8192 + (ocb+cl)*NS + slot] = v;
        }
    }
}

// ---------------- BN finalize from per-block partials ----------------
__global__ void bn_finalize(int C, int NS, float invN)
{
    int c = threadIdx.x;
    if (c >= C) return;
    float s = 0.f, q = 0.f;
    const float* ps = g_bnpart + (size_t)c*NS;
    const float* pq = g_bnpart + 8192 + (size_t)c*NS;
    for (int i=0;i<NS;i++) { s += ps[i]; q += pq[i]; }
    float m = s*invN;
    float var = q*invN - m*m;
    g_mean[c] = m;
    g_istd[c] = rsqrtf(var + 1e-5f);
}

// BN + ReLU -> split half2 planes (for next conv's input)
__global__ void bn_apply_split(const float* __restrict__ x, int nchLog, int hwLog)
{
    int idx = blockIdx.x*256 + threadIdx.x;
    int p  = idx & ((1<<hwLog)-1);
    int r  = idx >> hwLog;
    int ch = r & ((1<<nchLog)-1);
    int b  = r >> nchLog;
    int C  = 16 << nchLog;
    const float* xb = x + (((size_t)(b*C + ch*16)) << hwLog) + p;
    uint32_t h[8], l[8];
#pragma unroll
    for (int j=0;j<8;j++) {
        int c0 = ch*16 + 2*j;
        float f0 = xb[((size_t)(2*j))   << hwLog];
        float f1 = xb[((size_t)(2*j+1)) << hwLog];
        f0 = fmaxf((f0 - g_mean[c0  ])*g_istd[c0  ], 0.f);
        f1 = fmaxf((f1 - g_mean[c0+1])*g_istd[c0+1], 0.f);
        split2(f0, f1, h[j], l[j]);
    }
    size_t off = ((((size_t)b << nchLog) + ch) << hwLog) + p;
    uint4* H4 = (uint4*)g_aHi;
    uint4* L4 = (uint4*)g_aLo;
    H4[off*2]   = make_uint4(h[0],h[1],h[2],h[3]);
    H4[off*2+1] = make_uint4(h[4],h[5],h[6],h[7]);
    L4[off*2]   = make_uint4(l[0],l[1],l[2],l[3]);
    L4[off*2+1] = make_uint4(l[4],l[5],l[6],l[7]);
}

// in-place fp32 BN + ReLU (only before heads)
__global__ void bn_apply(float* __restrict__ x, int cMask, int hwShift)
{
    int idx = blockIdx.x*256 + threadIdx.x;
    int c = (idx >> (hwShift-2)) & cMask;
    float m = g_mean[c], is = g_istd[c];
    float4 v = ((float4*)x)[idx];
    v.x = fmaxf((v.x - m)*is, 0.f);
    v.y = fmaxf((v.y - m)*is, 0.f);
    v.z = fmaxf((v.z - m)*is, 0.f);
    v.w = fmaxf((v.w - m)*is, 0.f);
    ((float4*)x)[idx] = v;
}

// ---------------- heads (1x1 conv + bias + residual) ----------------
__global__ void head_coarse(const float* __restrict__ w, const float* __restrict__ bias,
                            float* __restrict__ out)
{
    __shared__ float sw[768];
    for (int idx=threadIdx.x; idx<768; idx+=256) sw[idx] = w[idx];
    __syncthreads();
    int i = blockIdx.x*256 + threadIdx.x;     // 16384
    int b = i>>12, p = i&4095;
    const float* xb = g_bufA + (size_t)b*256*4096 + p;
    float a0 = bias[0], a1 = bias[1], a2 = bias[2];
    for (int c=0;c<256;c++) {
        float v = xb[(size_t)c*4096];
        a0 = fmaf(v, sw[c],     a0);
        a1 = fmaf(v, sw[256+c], a1);
        a2 = fmaf(v, sw[512+c], a2);
    }
    out[(size_t)(b*3  )*4096 + p] = g_warp[(size_t)(b*2  )*4096 + p] + a0;
    out[(size_t)(b*3+1)*4096 + p] = g_warp[(size_t)(b*2+1)*4096 + p] + a1;
    out[(size_t)(b*3+2)*4096 + p] = a2;
}

// ---------------- 2x bilinear upsample (half-pixel, edge-clamped) ----------------
__global__ void upsample_kernel(const float* __restrict__ cm)
{
    int idx = blockIdx.x*256 + threadIdx.x;   // 196608
    if (idx >= 196608) return;
    int p  = idx & 16383;
    int bc = idx >> 14;
    int ox = p & 127, oy = p >> 7;
    float sx = 0.5f*ox - 0.25f;
    float sy = 0.5f*oy - 0.25f;
    float fx = floorf(sx), fy = floorf(sy);
    float ax = sx - fx, ay = sy - fy;
    int x0 = (int)fx, y0 = (int)fy;
    int x0c = max(x0,0), x1c = min(x0+1,63);
    int y0c = max(y0,0), y1c = min(y0+1,63);
    const float* inb = cm + (size_t)bc*4096;
    float v00 = inb[y0c*64+x0c], v01 = inb[y0c*64+x1c];
    float v10 = inb[y1c*64+x0c], v11 = inb[y1c*64+x1c];
    g_up[idx] = (1.f-ay)*((1.f-ax)*v00 + ax*v01) + ay*((1.f-ax)*v10 + ax*v11);
}

__global__ void head_fine(const float* __restrict__ w, const float* __restrict__ bias,
                          float* __restrict__ out)
{
    __shared__ float sw[192];
    for (int idx=threadIdx.x; idx<192; idx+=256) sw[idx] = w[idx];
    __syncthreads();
    int i = blockIdx.x*256 + threadIdx.x;     // 65536
    int b = i>>14, p = i&16383;
    const float* yb = g_bufA + (size_t)b*64*16384 + p;
    float a0 = bias[0], a1 = bias[1], a2 = bias[2];
    for (int c=0;c<64;c++) {
        float v = yb[(size_t)c*16384];
        a0 = fmaf(v, sw[c],      a0);
        a1 = fmaf(v, sw[64+c],   a1);
        a2 = fmaf(v, sw[128+c],  a2);
    }
    out[(size_t)(b*3  )*16384 + p] = g_up[(size_t)(b*3  )*16384 + p] + a0;
    out[(size_t)(b*3+1)*16384 + p] = g_up[(size_t)(b*3+1)*16384 + p] + a1;
    out[(size_t)(b*3+2)*16384 + p] = g_up[(size_t)(b*3+2)*16384 + p] + a2;
}

// ---------------- launch ----------------
extern "C" void kernel_launch(void* const* d_in, const int* in_sizes, int n_in,
                              void* d_out, int out_size)
{
    const float* f0c = (const float*)d_in[0];
    const float* f1c = (const float*)d_in[1];
    const float* f0f = (const float*)d_in[2];
    const float* f1f = (const float*)d_in[3];
    const float* cw1 = (const float*)d_in[4];
    const float* cw2 = (const float*)d_in[5];
    const float* cw3 = (const float*)d_in[6];
    const float* cw4 = (const float*)d_in[7];
    const float* cw5 = (const float*)d_in[8];
    const float* cb5 = (const float*)d_in[9];
    const float* fw1 = (const float*)d_in[10];
    const float* fw2 = (const float*)d_in[11];
    const float* fw3 = (const float*)d_in[12];
    const float* fw4 = (const float*)d_in[13];
    const float* fw5 = (const float*)d_in[14];
    const float* fb5 = (const float*)d_in[15];

    float *pA;
    uint32_t *pWH, *pWL, *pAH, *pAL;
    cudaGetSymbolAddress((void**)&pA,  g_bufA);
    cudaGetSymbolAddress((void**)&pWH, g_whi);
    cudaGetSymbolAddress((void**)&pWL, g_wlo);
    cudaGetSymbolAddress((void**)&pAH, g_aHi);
    cudaGetSymbolAddress((void**)&pAL, g_aLo);

    float* outC = (float*)d_out;          // (4,3,64,64)
    float* outF = outC + 49152;           // (4,3,128,128)

    // weight plane offsets (uint32 words)
    const int O1=0, O2=165888, O3=460800, O4=755712;
    const int F1=1050624, F2=1069056, F3=1087488, F4=1105920;
    wsplit16<<<648,256>>>(cw1, pWH+O1, pWL+O1, 130, 9, 165888);
    wsplit16<<<1152,256>>>(cw2, pWH+O2, pWL+O2, 256, 16, 294912);
    wsplit16<<<1152,256>>>(cw3, pWH+O3, pWL+O3, 256, 16, 294912);
    wsplit16<<<1152,256>>>(cw4, pWH+O4, pWL+O4, 256, 16, 294912);
    wsplit16<<<72,256>>>(fw1, pWH+F1, pWL+F1, 50, 4, 18432);
    wsplit16<<<72,256>>>(fw2, pWH+F2, pWL+F2, 64, 4, 18432);
    wsplit16<<<72,256>>>(fw3, pWH+F3, pWL+F3, 64, 4, 18432);
    wsplit16<<<72,256>>>(fw4, pWH+F4, pWL+F4, 64, 4, 18432);

    // coarse attention -> warp field
    attn_kernel<<<dim3(16,4,4),256>>>(f0c, f1c);
    attn_combine<<<64,256>>>();
    pack_coarse_split<<<dim3(64,9),256>>>(f0c, f1c);

    const float invNc = 1.0f/16384.0f;    // 4*4096
    const float invNf = 1.0f/65536.0f;    // 4*16384

    // coarse conv tower (NS = 8 tiles * 4 batch = 32 slots)
    conv16<9><<<dim3(8,8,4),256>>>(pAH, pAL, pWH+O1, pWL+O1, pA, 256, 64, 64, 32);
    bn_finalize<<<1,256>>>(256, 32, invNc);
    bn_apply_split<<<1024,256>>>(pA, 4, 12);
    conv16<16><<<dim3(8,8,4),256>>>(pAH, pAL, pWH+O2, pWL+O2, pA, 256, 64, 64, 32);
    bn_finalize<<<1,256>>>(256, 32, invNc);
    bn_apply_split<<<1024,256>>>(pA, 4, 12);
    conv16<16><<<dim3(8,8,4),256>>>(pAH, pAL, pWH+O3, pWL+O3, pA, 256, 64, 64, 32);
    bn_finalize<<<1,256>>>(256, 32, invNc);
    bn_apply_split<<<1024,256>>>(pA, 4, 12);
    conv16<16><<<dim3(8,8,4),256>>>(pAH, pAL, pWH+O4, pWL+O4, pA, 256, 64, 64, 32);
    bn_finalize<<<1,256>>>(256, 32, invNc);
    bn_apply<<<4096,256>>>(pA, 255, 12);

    head_coarse<<<64,256>>>(cw5, cb5, outC);

    // fine stage
    upsample_kernel<<<768,256>>>(outC);
    pack_fine_split<<<dim3(256,4),256>>>(f0f, f1f);

    // fine conv tower (NS = 32 tiles * 4 batch = 128 slots)
    conv16<4><<<dim3(32,2,4),256>>>(pAH, pAL, pWH+F1, pWL+F1, pA, 64, 128, 128, 128);
    bn_finalize<<<1,256>>>(64, 128, invNf);
    bn_apply_split<<<1024,256>>>(pA, 2, 14);
    conv16<4><<<dim3(32,2,4),256>>>(pAH, pAL, pWH+F2, pWL+F2, pA, 64, 128, 128, 128);
    bn_finalize<<<1,256>>>(64, 128, invNf);
    bn_apply_split<<<1024,256>>>(pA, 2, 14);
    conv16<4><<<dim3(32,2,4),256>>>(pAH, pAL, pWH+F3, pWL+F3, pA, 64, 128, 128, 128);
    bn_finalize<<<1,256>>>(64, 128, invNf);
    bn_apply_split<<<1024,256>>>(pA, 2, 14);
    conv16<4><<<dim3(32,2,4),256>>>(pAH, pAL, pWH+F4, pWL+F4, pA, 64, 128, 128, 128);
    bn_finalize<<<1,256>>>(64, 128, invNf);
    bn_apply<<<4096,256>>>(pA, 63, 14);

    head_fine<<<256,256>>>(fw5, fb5, outF);
}

// round 17
// speedup vs baseline: 1.2090x; 1.2090x over previous
#include <cuda_runtime.h>
#include <cuda_fp16.h>
#include <cstdint>
#include <math.h>

// ---------------- scratch (static __device__, no allocation) ----------------
__device__ float g_part[4*4*3*4096];     // attention partials [b][ks][3][q]
__device__ float g_warp[4*2*4096];       // coarse_warp [b][2][p]
__device__ float g_bufA[4194304];        // conv output (fp32)
__device__ float g_up[4*3*16384];        // upsampled coarse matches
__device__ float g_mean[256];
__device__ float g_istd[256];
__device__ uint32_t g_whi[1124352];      // packed fp16-hi weight planes (half2)
__device__ uint32_t g_wlo[1124352];      // packed fp16-lo weight planes
__device__ __align__(16) uint32_t g_aHi[2097152];  // activation hi planes
__device__ __align__(16) uint32_t g_aLo[2097152];  // activation lo planes

// ---------------- cp.async helpers ----------------
__device__ __forceinline__ uint32_t smem_u32(const void* p) {
    return (uint32_t)__cvta_generic_to_shared(p);
}
__device__ __forceinline__ void cp_async16(uint32_t dst, const void* src, int srcsz) {
    asm volatile("cp.async.ca.shared.global [%0], [%1], 16, %2;\n"
                 :: "r"(dst), "l"(src), "r"(srcsz));
}
__device__ __forceinline__ void cp_commit() {
    asm volatile("cp.async.commit_group;\n");
}
__device__ __forceinline__ void cp_wait1() {
    asm volatile("cp.async.wait_group 1;\n");
}
__device__ __forceinline__ void cp_wait0() {
    asm volatile("cp.async.wait_group 0;\n");
}

// ---------------- fp16 mma / ldmatrix / split helpers ----------------
__device__ __forceinline__ void mma_f16(float* c, const uint32_t* a, const uint32_t* b) {
    asm volatile("mma.sync.aligned.m16n8k16.row.col.f32.f16.f16.f32 "
        "{%0,%1,%2,%3}, {%4,%5,%6,%7}, {%8,%9}, {%0,%1,%2,%3};"
        : "+f"(c[0]), "+f"(c[1]), "+f"(c[2]), "+f"(c[3])
        : "r"(a[0]), "r"(a[1]), "r"(a[2]), "r"(a[3]), "r"(b[0]), "r"(b[1]));
}
__device__ __forceinline__ void ldsm_x4(uint32_t& r0, uint32_t& r1, uint32_t& r2,
                                        uint32_t& r3, uint32_t addr) {
    asm volatile("ldmatrix.sync.aligned.m8n8.x4.shared.b16 {%0,%1,%2,%3}, [%4];"
        : "=r"(r0), "=r"(r1), "=r"(r2), "=r"(r3) : "r"(addr));
}
__device__ __forceinline__ void split2(float f0, float f1, uint32_t& hi, uint32_t& lo) {
    __half h0 = __float2half_rn(f0), h1 = __float2half_rn(f1);
    __half2 hh = __halves2half2(h0, h1);
    __half2 ll = __halves2half2(__float2half_rn(f0 - __half2float(h0)),
                                __float2half_rn(f1 - __half2float(h1)));
    hi = *(uint32_t*)&hh;
    lo = *(uint32_t*)&ll;
}

// ---------------- weight pre-split into packed chunk planes ----------------
__global__ void wsplit16(const float* __restrict__ w, uint32_t* __restrict__ hi,
                         uint32_t* __restrict__ lo, int cinReal, int nch, int n)
{
    int idx = blockIdx.x*256 + threadIdx.x;
    if (idx >= n) return;
    int p  = idx & 7;
    int r1 = idx >> 3;
    int o  = r1 & 31;
    int r2 = r1 >> 5;
    int k  = r2 % 9;
    int r3 = r2 / 9;
    int ch = r3 % nch;
    int ob = r3 / nch;
    int oc = ob*32 + o;
    int ic0 = ch*16 + 2*p;
    float f0 = (ic0   < cinReal) ? w[((size_t)oc*cinReal + ic0  )*9 + k] : 0.f;
    float f1 = (ic0+1 < cinReal) ? w[((size_t)oc*cinReal + ic0+1)*9 + k] : 0.f;
    split2(f0, f1, hi[idx], lo[idx]);
}

// ---------------- Q/K pre-split: [b][64ch][4096px] fp32 -> [b][px][32w] ----
__global__ void qksplit(const float* __restrict__ src, uint32_t* __restrict__ dHi,
                        uint32_t* __restrict__ dLo)
{
    int i = blockIdx.x*256 + threadIdx.x;      // 16384 = b*4096+pix
    if (i >= 16384) return;
    int b = i>>12, p = i&4095;
    const float* sb = src + (size_t)b*262144;
    uint4* H4 = (uint4*)(dHi + (size_t)i*32);
    uint4* L4 = (uint4*)(dLo + (size_t)i*32);
#pragma unroll
    for (int j4=0;j4<8;j4++) {
        uint32_t h[4], l[4];
#pragma unroll
        for (int e=0;e<4;e++) {
            int c = j4*8 + 2*e;
            split2(sb[(size_t)c*4096 + p], sb[(size_t)(c+1)*4096 + p], h[e], l[e]);
        }
        H4[j4] = make_uint4(h[0],h[1],h[2],h[3]);
        L4[j4] = make_uint4(l[0],l[1],l[2],l[3]);
    }
}

// ---------------- fp16 tensor-core attention: QK^T -> exp -> expectation ----
// grid (32 qtiles, 2 key-slices, 4 batch), 256 thr. Block: 128 q x 2048 keys.
// A (Q) fragments preloaded once; K staged per 64-key chunk via cp.async.
__global__ void __launch_bounds__(256) attn_mma(
    const uint32_t* __restrict__ qHi, const uint32_t* __restrict__ qLo,
    const uint32_t* __restrict__ kHi, const uint32_t* __restrict__ kLo)
{
    __shared__ __align__(16) uint32_t sQH[128*36];
    __shared__ __align__(16) uint32_t sQL[128*36];
    __shared__ __align__(16) uint32_t sKH[2][64*36];
    __shared__ __align__(16) uint32_t sKL[2][64*36];
    const int qt = blockIdx.x, ks = blockIdx.y, b = blockIdx.z;
    const int tid = threadIdx.x;
    const int lane = tid & 31;
    const int wid = tid >> 5;
    const int g = lane >> 2;
    const int t = lane & 3;
    const int w16 = wid << 4;

    // stage Q tile (128 rows x 32 words, both planes)
    for (int idx=tid; idx<2048; idx+=256) {
        int h   = idx & 7;
        int row = (idx>>3) & 127;
        int pl  = idx >> 10;
        const uint32_t* src = (pl ? qLo : qHi) +
            ((size_t)(b*4096 + qt*128 + row)*32 + h*4);
        uint32_t dst = smem_u32((pl ? sQL : sQH) + row*36 + h*4);
        cp_async16(dst, src, 16);
    }
    // stage K chunk 0
    auto stageK = [&](int buf, int ck) {
        for (int idx=tid; idx<1024; idx+=256) {
            int h   = idx & 7;
            int row = (idx>>3) & 63;
            int pl  = idx >> 9;
            const uint32_t* src = (pl ? kLo : kHi) +
                ((size_t)(b*4096 + ks*2048 + ck*64 + row)*32 + h*4);
            uint32_t dst = smem_u32((pl ? sKL[buf] : sKH[buf]) + row*36 + h*4);
            cp_async16(dst, src, 16);
        }
    };
    stageK(0, 0);
    cp_commit();
    cp_wait0();
    __syncthreads();

    // preload A (Q) fragments: 4 k-chunks x 4 regs, both planes
    uint32_t AH[4][4], AL[4][4];
#pragma unroll
    for (int kc=0;kc<4;kc++) {
        int r0 = (w16+g)*36 + kc*8 + t;
        int r1 = (w16+8+g)*36 + kc*8 + t;
        AH[kc][0]=sQH[r0];   AH[kc][1]=sQH[r1];
        AH[kc][2]=sQH[r0+4]; AH[kc][3]=sQH[r1+4];
        AL[kc][0]=sQL[r0];   AL[kc][1]=sQL[r1];
        AL[kc][2]=sQL[r0+4]; AL[kc][3]=sQL[r1+4];
    }

    // ldmatrix B addressing (R15-verified mapping)
    const int j  = lane >> 3;
    const int lr = lane & 7;
    const int rowB = 8*(j>>1) + lr;      // 0..15
    const int hw = (j & 1) * 4;

    const float gxt = (float)(2*t)*0.03125f - 0.984375f;
    float aE[2] = {0.f,0.f}, aX[2] = {0.f,0.f}, aY[2] = {0.f,0.f};

    for (int ci=0; ci<32; ci++) {
        if (ci+1 < 32) {
            stageK((ci+1)&1, ci+1);
            cp_commit();
        }
        const int buf = ci & 1;
        float c[8][4];
#pragma unroll
        for (int n=0;n<8;n++)
#pragma unroll
            for (int e=0;e<4;e++) c[n][e] = 0.f;
#pragma unroll
        for (int kc=0;kc<4;kc++) {
#pragma unroll
            for (int np=0;np<4;np++) {
                int base = (np*16 + rowB)*36 + kc*8 + hw;
                uint32_t h0,h1,h2,h3, l0,l1,l2,l3;
                ldsm_x4(h0,h1,h2,h3, smem_u32(sKH[buf] + base));
                ldsm_x4(l0,l1,l2,l3, smem_u32(sKL[buf] + base));
                uint32_t BH0[2]={h0,h1}, BH1[2]={h2,h3};
                uint32_t BL0[2]={l0,l1}, BL1[2]={l2,l3};
                mma_f16(c[2*np],   AH[kc], BH0);
                mma_f16(c[2*np],   AH[kc], BL0);
                mma_f16(c[2*np],   AL[kc], BH0);
                mma_f16(c[2*np+1], AH[kc], BH1);
                mma_f16(c[2*np+1], AH[kc], BL1);
                mma_f16(c[2*np+1], AL[kc], BH1);
            }
        }
        const float gyv = (float)(ks*32 + ci)*0.03125f - 0.984375f;
#pragma unroll
        for (int n=0;n<8;n++) {
            float gx0 = gxt + 0.25f*n;
            float gx1 = gx0 + 0.03125f;
            float e0 = __expf(c[n][0]*0.125f);
            float e1 = __expf(c[n][1]*0.125f);
            float e2 = __expf(c[n][2]*0.125f);
            float e3 = __expf(c[n][3]*0.125f);
            float s0 = e0+e1, s1 = e2+e3;
            aE[0] += s0;
            aX[0] = fmaf(e0,gx0, fmaf(e1,gx1, aX[0]));
            aY[0] = fmaf(s0, gyv, aY[0]);
            aE[1] += s1;
            aX[1] = fmaf(e2,gx0, fmaf(e3,gx1, aX[1]));
            aY[1] = fmaf(s1, gyv, aY[1]);
        }
        if (ci+1 < 32) {
            cp_wait0();
            __syncthreads();
        }
    }

    // reduce across the 4 column-lanes (t)
#pragma unroll
    for (int mask=1; mask<4; mask<<=1) {
#pragma unroll
        for (int r=0;r<2;r++) {
            aE[r] += __shfl_xor_sync(0xffffffffu, aE[r], mask);
            aX[r] += __shfl_xor_sync(0xffffffffu, aX[r], mask);
            aY[r] += __shfl_xor_sync(0xffffffffu, aY[r], mask);
        }
    }
    if (t == 0) {
        size_t base = ((size_t)(b*2+ks)*3)*4096;
        int q0 = qt*128 + w16 + g;
        g_part[base        + q0] = aE[0];
        g_part[base + 4096 + q0] = aX[0];
        g_part[base + 8192 + q0] = aY[0];
        int q1 = q0 + 8;
        g_part[base        + q1] = aE[1];
        g_part[base + 4096 + q1] = aX[1];
        g_part[base + 8192 + q1] = aY[1];
    }
}

__global__ void attn_combine2()
{
    int i = blockIdx.x*256 + threadIdx.x;      // 16384
    if (i >= 16384) return;
    int b = i>>12, q = i&4095;
    size_t b0 = ((size_t)(b*2  )*3)*4096;
    size_t b1 = ((size_t)(b*2+1)*3)*4096;
    float sE = g_part[b0+q]      + g_part[b1+q];
    float sX = g_part[b0+4096+q] + g_part[b1+4096+q];
    float sY = g_part[b0+8192+q] + g_part[b1+8192+q];
    float inv = 1.0f/sE;
    g_warp[(size_t)(b*2  )*4096 + q] = sX*inv;
    g_warp[(size_t)(b*2+1)*4096 + q] = sY*inv;
}

// ---------------- coarse concat + grid_sample -> split planes (nch=9) ------
__global__ void pack_coarse_split(const float* __restrict__ f0c,
                                  const float* __restrict__ f1c)
{
    int i = blockIdx.x*256 + threadIdx.x;      // 16384
    if (i >= 16384) return;
    int b = i>>12, p = i&4095;
    int ch = blockIdx.y;                       // 0..8
    float wx = g_warp[(size_t)(b*2  )*4096 + p];
    float wy = g_warp[(size_t)(b*2+1)*4096 + p];

    float vals[16];
    if (ch < 4) {
        const float* f0b = f0c + (size_t)b*262144;
#pragma unroll
        for (int j=0;j<16;j++) vals[j] = f0b[(size_t)(ch*16+j)*4096 + p];
    } else if (ch < 8) {
        float fx = (wx + 1.f)*32.f - 0.5f;
        float fy = (wy + 1.f)*32.f - 0.5f;
        float flx = floorf(fx), fly = floorf(fy);
        float ax = fx - flx, ay = fy - fly;
        int xi = (int)flx, yi = (int)fly;
        float vx0 = ((unsigned)xi     < 64u) ? 1.f : 0.f;
        float vx1 = ((unsigned)(xi+1) < 64u) ? 1.f : 0.f;
        float vy0 = ((unsigned)yi     < 64u) ? 1.f : 0.f;
        float vy1 = ((unsigned)(yi+1) < 64u) ? 1.f : 0.f;
        int cx0 = min(max(xi,0),63),   cx1 = min(max(xi+1,0),63);
        int cy0 = min(max(yi,0),63),   cy1 = min(max(yi+1,0),63);
        float w00 = (1.f-ax)*(1.f-ay)*vx0*vy0;
        float w01 = ax*(1.f-ay)*vx1*vy0;
        float w10 = (1.f-ax)*ay*vx0*vy1;
        float w11 = ax*ay*vx1*vy1;
        int i00 = cy0*64+cx0, i01 = cy0*64+cx1, i10 = cy1*64+cx0, i11 = cy1*64+cx1;
        const float* f1b = f1c + (size_t)b*262144;
#pragma unroll
        for (int j=0;j<16;j++) {
            const float* fc = f1b + (size_t)((ch-4)*16+j)*4096;
            vals[j] = w00*fc[i00] + w01*fc[i01] + w10*fc[i10] + w11*fc[i11];
        }
    } else {
#pragma unroll
        for (int j=0;j<16;j++) vals[j] = 0.f;
        vals[0] = wx; vals[1] = wy;
    }

    uint32_t h[8], l[8];
#pragma unroll
    for (int j=0;j<8;j++) split2(vals[2*j], vals[2*j+1], h[j], l[j]);
    size_t off = (((size_t)(b*9 + ch)) << 12) + p;
    uint4* H4 = (uint4*)g_aHi;
    uint4* L4 = (uint4*)g_aLo;
    H4[off*2]   = make_uint4(h[0],h[1],h[2],h[3]);
    H4[off*2+1] = make_uint4(h[4],h[5],h[6],h[7]);
    L4[off*2]   = make_uint4(l[0],l[1],l[2],l[3]);
    L4[off*2+1] = make_uint4(l[4],l[5],l[6],l[7]);
}

// ---------------- fine concat + grid_sample -> split planes (nch=4) --------
__global__ void pack_fine_split(const float* __restrict__ f0f,
                                const float* __restrict__ f1f)
{
    int i = blockIdx.x*256 + threadIdx.x;      // 65536
    if (i >= 65536) return;
    int b = i>>14, p = i&16383;
    int ch = blockIdx.y;                       // 0..3
    float wx = g_up[(size_t)(b*3  )*16384 + p];
    float wy = g_up[(size_t)(b*3+1)*16384 + p];

    float w00=0,w01=0,w10=0,w11=0;
    int i00=0,i01=0,i10=0,i11=0;
    if (ch == 1 || ch == 2) {
        float fx = (wx + 1.f)*64.f - 0.5f;
        float fy = (wy + 1.f)*64.f - 0.5f;
        float flx = floorf(fx), fly = floorf(fy);
        float ax = fx - flx, ay = fy - fly;
        int xi = (int)flx, yi = (int)fly;
        float vx0 = ((unsigned)xi     < 128u) ? 1.f : 0.f;
        float vx1 = ((unsigned)(xi+1) < 128u) ? 1.f : 0.f;
        float vy0 = ((unsigned)yi     < 128u) ? 1.f : 0.f;
        float vy1 = ((unsigned)(yi+1) < 128u) ? 1.f : 0.f;
        int cx0 = min(max(xi,0),127),  cx1 = min(max(xi+1,0),127);
        int cy0 = min(max(yi,0),127),  cy1 = min(max(yi+1,0),127);
        w00 = (1.f-ax)*(1.f-ay)*vx0*vy0;
        w01 = ax*(1.f-ay)*vx1*vy0;
        w10 = (1.f-ax)*ay*vx0*vy1;
        w11 = ax*ay*vx1*vy1;
        i00 = cy0*128+cx0; i01 = cy0*128+cx1; i10 = cy1*128+cx0; i11 = cy1*128+cx1;
    }
    const float* f0b = f0f + (size_t)b*24*16384;
    const float* f1b = f1f + (size_t)b*24*16384;

    float vals[16];
#pragma unroll
    for (int j=0;j<16;j++) {
        int c = ch*16 + j;
        float v;
        if (c < 24) {
            v = f0b[(size_t)c*16384 + p];
        } else if (c < 48) {
            const float* fc = f1b + (size_t)(c-24)*16384;
            v = w00*fc[i00] + w01*fc[i01] + w10*fc[i10] + w11*fc[i11];
        } else if (c == 48) v = wx;
        else if (c == 49) v = wy;
        else v = 0.f;
        vals[j] = v;
    }

    uint32_t h[8], l[8];
#pragma unroll
    for (int j=0;j<8;j++) split2(vals[2*j], vals[2*j+1], h[j], l[j]);
    size_t off = (((size_t)(b*4 + ch)) << 14) + p;
    uint4* H4 = (uint4*)g_aHi;
    uint4* L4 = (uint4*)g_aLo;
    H4[off*2]   = make_uint4(h[0],h[1],h[2],h[3]);
    H4[off*2+1] = make_uint4(h[4],h[5],h[6],h[7]);
    L4[off*2]   = make_uint4(l[0],l[1],l[2],l[3]);
    L4[off*2+1] = make_uint4(l[4],l[5],l[6],l[7]);
}

// ---------------- fp16 m16n8k16 tensor-core 3x3 conv (R14 version) ----------
template<int NCH>
__global__ void __launch_bounds__(256,2) conv16(
    const uint32_t* __restrict__ aHi, const uint32_t* __restrict__ aLo,
    const uint32_t* __restrict__ wHi, const uint32_t* __restrict__ wLo,
    float* __restrict__ out, int cout, int H, int W)
{
    __shared__ __align__(16) uint32_t sInH[2][18][34][8];
    __shared__ __align__(16) uint32_t sInL[2][18][34][8];
    __shared__ __align__(16) uint32_t sWH[2][9][32][8];
    __shared__ __align__(16) uint32_t sWL[2][9][32][8];
    const int HW = H*W;
    const int tilesX = W >> 5;
    const int tx = blockIdx.x % tilesX;
    const int ty = blockIdx.x / tilesX;
    const int ob = blockIdx.y;
    const int ocb = ob << 5;
    const int b = blockIdx.z;
    const int tid = threadIdx.x;
    const int lane = tid & 31;
    const int wid = tid >> 5;
    const int g = lane >> 2;
    const int t = lane & 3;
    const int x0 = tx << 5, y0 = ty << 4;

    auto stage = [&](int buf, int ch) {
        const size_t inBase = ((size_t)(b*NCH + ch))*HW;
        for (int idx=tid; idx<2448; idx+=256) {
            int pl = idx & 1;
            int h  = (idx>>1)&1;
            int e  = idx>>2;
            int x  = e % 34;
            int r  = e / 34;
            int yy = y0-1+r, xx = x0-1+x;
            bool ok = ((unsigned)yy < (unsigned)H) && ((unsigned)xx < (unsigned)W);
            int yc = min(max(yy,0),H-1), xc = min(max(xx,0),W-1);
            const uint32_t* src = (pl ? aLo : aHi) + (inBase + yc*W + xc)*8 + h*4;
            int ph = (h ^ ((x>>2)&1)) << 2;
            uint32_t dst = smem_u32(pl ? &sInL[buf][r][x][ph] : &sInH[buf][r][x][ph]);
            cp_async16(dst, src, ok ? 16 : 0);
        }
        const size_t wBase = ((size_t)(ob*NCH + ch))*2304;
        for (int idx=tid; idx<1152; idx+=256) {
            int pl = idx & 1;
            int h  = (idx>>1)&1;
            int e  = idx>>2;
            int o  = e & 31;
            int k  = e >> 5;
            const uint32_t* src = (pl ? wLo : wHi) + wBase + (size_t)(k*32 + o)*8 + h*4;
            int ph = (h ^ ((o>>2)&1)) << 2;
            uint32_t dst = smem_u32(pl ? &sWL[buf][k][o][ph] : &sWH[buf][k][o][ph]);
            cp_async16(dst, src, 16);
        }
        cp_commit();
    };

    float c[2][2][4][4];
#pragma unroll
    for (int rr=0;rr<2;rr++)
#pragma unroll
        for (int m=0;m<2;m++)
#pragma unroll
            for (int n=0;n<4;n++)
#pragma unroll
                for (int e=0;e<4;e++) c[rr][m][n][e] = 0.f;

    stage(0, 0);

    for (int ci=0; ci<NCH; ci++) {
        if (ci+1 < NCH) {
            stage((ci+1)&1, ci+1);
            cp_wait1();
        } else {
            cp_wait0();
        }
        __syncthreads();
        const int buf = ci & 1;
        const int cg = t ^ (g & 4);
        const int cg4 = cg ^ 4;
#pragma unroll
        for (int kh=0;kh<3;kh++) {
#pragma unroll
            for (int kw=0;kw<3;kw++) {
                const uint32_t* wh = &sWH[buf][kh*3+kw][0][0];
                const uint32_t* wl = &sWL[buf][kh*3+kw][0][0];
                uint32_t BH[4][2], BL[4][2];
#pragma unroll
                for (int n=0;n<4;n++) {
                    int ro = (8*n+g)*8;
                    BH[n][0] = wh[ro+cg];  BH[n][1] = wh[ro+cg4];
                    BL[n][0] = wl[ro+cg];  BL[n][1] = wl[ro+cg4];
                }
#pragma unroll
                for (int rr=0;rr<2;rr++) {
                    int r = 2*wid + rr + kh;
                    const uint32_t* rh = &sInH[buf][r][0][0];
                    const uint32_t* rl = &sInL[buf][r][0][0];
#pragma unroll
                    for (int m=0;m<2;m++) {
                        int xa = 16*m + kw + g;
                        int ca = t ^ (xa & 4);
                        int ca4 = ca ^ 4;
                        int base0 = xa*8;
                        uint32_t AH[4] = { rh[base0+ca], rh[base0+64+ca],
                                           rh[base0+ca4], rh[base0+64+ca4] };
                        uint32_t AL[4] = { rl[base0+ca], rl[base0+64+ca],
                                           rl[base0+ca4], rl[base0+64+ca4] };
#pragma unroll
                        for (int n=0;n<4;n++) {
                            mma_f16(c[rr][m][n], AH, BH[n]);
                            mma_f16(c[rr][m][n], AH, BL[n]);
                            mma_f16(c[rr][m][n], AL, BH[n]);
                        }
                    }
                }
            }
        }
        __syncthreads();
    }

#pragma unroll
    for (int rr=0;rr<2;rr++) {
        const int oy = y0 + 2*wid + rr;
#pragma unroll
        for (int m=0;m<2;m++) {
#pragma unroll
            for (int n=0;n<4;n++) {
                int oc = ocb + 8*n + 2*t;
                float* p0 = out + ((size_t)b*cout + oc)*HW + oy*W + x0 + 16*m + g;
                p0[0] = c[rr][m][n][0];
                p0[8] = c[rr][m][n][2];
                float* p1 = p0 + HW;
                p1[0] = c[rr][m][n][1];
                p1[8] = c[rr][m][n][3];
            }
        }
    }
}

// ---------------- batch-norm: per-channel stats over (B,H,W) ----------------
__global__ void bn_reduce(const float* __restrict__ x, int C, int HW)
{
    const int c = blockIdx.x;
    const int tid = threadIdx.x;
    const int HW4 = HW >> 2;
    float s = 0.f, s2 = 0.f;
    for (int b=0;b<4;b++) {
        const float4* xb = (const float4*)(x + ((size_t)b*C + c)*HW);
        for (int p=tid; p<HW4; p+=256) {
            float4 v = xb[p];
            s  += v.x + v.y + v.z + v.w;
            s2 += v.x*v.x + v.y*v.y + v.z*v.z + v.w*v.w;
        }
    }
    __shared__ float rs[256];
    __shared__ float rq[256];
    rs[tid] = s; rq[tid] = s2;
    __syncthreads();
    for (int off=128; off>0; off>>=1) {
        if (tid < off) { rs[tid]+=rs[tid+off]; rq[tid]+=rq[tid+off]; }
        __syncthreads();
    }
    if (tid == 0) {
        float invN = 1.0f/(4.0f*HW);
        float m = rs[0]*invN;
        float var = rq[0]*invN - m*m;
        g_mean[c] = m;
        g_istd[c] = rsqrtf(var + 1e-5f);
    }
}

// BN + ReLU -> split half2 planes (for next conv's input)
__global__ void bn_apply_split(const float* __restrict__ x, int nchLog, int hwLog)
{
    int idx = blockIdx.x*256 + threadIdx.x;
    int p  = idx & ((1<<hwLog)-1);
    int r  = idx >> hwLog;
    int ch = r & ((1<<nchLog)-1);
    int b  = r >> nchLog;
    int C  = 16 << nchLog;
    const float* xb = x + (((size_t)(b*C + ch*16)) << hwLog) + p;
    uint32_t h[8], l[8];
#pragma unroll
    for (int j=0;j<8;j++) {
        int c0 = ch*16 + 2*j;
        float f0 = xb[((size_t)(2*j))   << hwLog];
        float f1 = xb[((size_t)(2*j+1)) << hwLog];
        f0 = fmaxf((f0 - g_mean[c0  ])*g_istd[c0  ], 0.f);
        f1 = fmaxf((f1 - g_mean[c0+1])*g_istd[c0+1], 0.f);
        split2(f0, f1, h[j], l[j]);
    }
    size_t off = ((((size_t)b << nchLog) + ch) << hwLog) + p;
    uint4* H4 = (uint4*)g_aHi;
    uint4* L4 = (uint4*)g_aLo;
    H4[off*2]   = make_uint4(h[0],h[1],h[2],h[3]);
    H4[off*2+1] = make_uint4(h[4],h[5],h[6],h[7]);
    L4[off*2]   = make_uint4(l[0],l[1],l[2],l[3]);
    L4[off*2+1] = make_uint4(l[4],l[5],l[6],l[7]);
}

// in-place fp32 BN + ReLU (only before heads)
__global__ void bn_apply(float* __restrict__ x, int cMask, int hwShift)
{
    int idx = blockIdx.x*256 + threadIdx.x;
    int c = (idx >> (hwShift-2)) & cMask;
    float m = g_mean[c], is = g_istd[c];
    float4 v = ((float4*)x)[idx];
    v.x = fmaxf((v.x - m)*is, 0.f);
    v.y = fmaxf((v.y - m)*is, 0.f);
    v.z = fmaxf((v.z - m)*is, 0.f);
    v.w = fmaxf((v.w - m)*is, 0.f);
    ((float4*)x)[idx] = v;
}

// ---------------- heads (1x1 conv + bias + residual) ----------------
__global__ void head_coarse(const float* __restrict__ w, const float* __restrict__ bias,
                            float* __restrict__ out)
{
    __shared__ float sw[768];
    for (int idx=threadIdx.x; idx<768; idx+=256) sw[idx] = w[idx];
    __syncthreads();
    int i = blockIdx.x*256 + threadIdx.x;     // 16384
    int b = i>>12, p = i&4095;
    const float* xb = g_bufA + (size_t)b*256*4096 + p;
    float a0 = bias[0], a1 = bias[1], a2 = bias[2];
    for (int c=0;c<256;c++) {
        float v = xb[(size_t)c*4096];
        a0 = fmaf(v, sw[c],     a0);
        a1 = fmaf(v, sw[256+c], a1);
        a2 = fmaf(v, sw[512+c], a2);
    }
    out[(size_t)(b*3  )*4096 + p] = g_warp[(size_t)(b*2  )*4096 + p] + a0;
    out[(size_t)(b*3+1)*4096 + p] = g_warp[(size_t)(b*2+1)*4096 + p] + a1;
    out[(size_t)(b*3+2)*4096 + p] = a2;
}

// ---------------- 2x bilinear upsample (half-pixel, edge-clamped) ----------------
__global__ void upsample_kernel(const float* __restrict__ cm)
{
    int idx = blockIdx.x*256 + threadIdx.x;   // 196608
    if (idx >= 196608) return;
    int p  = idx & 16383;
    int bc = idx >> 14;
    int ox = p & 127, oy = p >> 7;
    float sx = 0.5f*ox - 0.25f;
    float sy = 0.5f*oy - 0.25f;
    float fx = floorf(sx), fy = floorf(sy);
    float ax = sx - fx, ay = sy - fy;
    int x0 = (int)fx, y0 = (int)fy;
    int x0c = max(x0,0), x1c = min(x0+1,63);
    int y0c = max(y0,0), y1c = min(y0+1,63);
    const float* inb = cm + (size_t)bc*4096;
    float v00 = inb[y0c*64+x0c], v01 = inb[y0c*64+x1c];
    float v10 = inb[y1c*64+x0c], v11 = inb[y1c*64+x1c];
    g_up[idx] = (1.f-ay)*((1.f-ax)*v00 + ax*v01) + ay*((1.f-ax)*v10 + ax*v11);
}

__global__ void head_fine(const float* __restrict__ w, const float* __restrict__ bias,
                          float* __restrict__ out)
{
    __shared__ float sw[192];
    for (int idx=threadIdx.x; idx<192; idx+=256) sw[idx] = w[idx];
    __syncthreads();
    int i = blockIdx.x*256 + threadIdx.x;     // 65536
    int b = i>>14, p = i&16383;
    const float* yb = g_bufA + (size_t)b*64*16384 + p;
    float a0 = bias[0], a1 = bias[1], a2 = bias[2];
    for (int c=0;c<64;c++) {
        float v = yb[(size_t)c*16384];
        a0 = fmaf(v, sw[c],      a0);
        a1 = fmaf(v, sw[64+c],   a1);
        a2 = fmaf(v, sw[128+c],  a2);
    }
    out[(size_t)(b*3  )*16384 + p] = g_up[(size_t)(b*3  )*16384 + p] + a0;
    out[(size_t)(b*3+1)*16384 + p] = g_up[(size_t)(b*3+1)*16384 + p] + a1;
    out[(size_t)(b*3+2)*16384 + p] = g_up[(size_t)(b*3+2)*16384 + p] + a2;
}

// ---------------- launch ----------------
extern "C" void kernel_launch(void* const* d_in, const int* in_sizes, int n_in,
                              void* d_out, int out_size)
{
    const float* f0c = (const float*)d_in[0];
    const float* f1c = (const float*)d_in[1];
    const float* f0f = (const float*)d_in[2];
    const float* f1f = (const float*)d_in[3];
    const float* cw1 = (const float*)d_in[4];
    const float* cw2 = (const float*)d_in[5];
    const float* cw3 = (const float*)d_in[6];
    const float* cw4 = (const float*)d_in[7];
    const float* cw5 = (const float*)d_in[8];
    const float* cb5 = (const float*)d_in[9];
    const float* fw1 = (const float*)d_in[10];
    const float* fw2 = (const float*)d_in[11];
    const float* fw3 = (const float*)d_in[12];
    const float* fw4 = (const float*)d_in[13];
    const float* fw5 = (const float*)d_in[14];
    const float* fb5 = (const float*)d_in[15];

    float *pA;
    uint32_t *pWH, *pWL, *pAH, *pAL;
    cudaGetSymbolAddress((void**)&pA,  g_bufA);
    cudaGetSymbolAddress((void**)&pWH, g_whi);
    cudaGetSymbolAddress((void**)&pWL, g_wlo);
    cudaGetSymbolAddress((void**)&pAH, g_aHi);
    cudaGetSymbolAddress((void**)&pAL, g_aLo);

    float* outC = (float*)d_out;          // (4,3,64,64)
    float* outF = outC + 49152;           // (4,3,128,128)

    // weight plane offsets (uint32 words)
    const int O1=0, O2=165888, O3=460800, O4=755712;
    const int F1=1050624, F2=1069056, F3=1087488, F4=1105920;
    wsplit16<<<648,256>>>(cw1, pWH+O1, pWL+O1, 130, 9, 165888);
    wsplit16<<<1152,256>>>(cw2, pWH+O2, pWL+O2, 256, 16, 294912);
    wsplit16<<<1152,256>>>(cw3, pWH+O3, pWL+O3, 256, 16, 294912);
    wsplit16<<<1152,256>>>(cw4, pWH+O4, pWL+O4, 256, 16, 294912);
    wsplit16<<<72,256>>>(fw1, pWH+F1, pWL+F1, 50, 4, 18432);
    wsplit16<<<72,256>>>(fw2, pWH+F2, pWL+F2, 64, 4, 18432);
    wsplit16<<<72,256>>>(fw3, pWH+F3, pWL+F3, 64, 4, 18432);
    wsplit16<<<72,256>>>(fw4, pWH+F4, pWL+F4, 64, 4, 18432);

    // coarse attention (tensor-core) -> warp field
    qksplit<<<64,256>>>(f0c, pAH, pAL);
    qksplit<<<64,256>>>(f1c, pAH+524288, pAL+524288);
    attn_mma<<<dim3(32,2,4),256>>>(pAH, pAL, pAH+524288, pAL+524288);
    attn_combine2<<<64,256>>>();
    pack_coarse_split<<<dim3(64,9),256>>>(f0c, f1c);

    // coarse conv tower
    conv16<9><<<dim3(8,8,4),256>>>(pAH, pAL, pWH+O1, pWL+O1, pA, 256, 64, 64);
    bn_reduce<<<256,256>>>(pA, 256, 4096);
    bn_apply_split<<<1024,256>>>(pA, 4, 12);
    conv16<16><<<dim3(8,8,4),256>>>(pAH, pAL, pWH+O2, pWL+O2, pA, 256, 64, 64);
    bn_reduce<<<256,256>>>(pA, 256, 4096);
    bn_apply_split<<<1024,256>>>(pA, 4, 12);
    conv16<16><<<dim3(8,8,4),256>>>(pAH, pAL, pWH+O3, pWL+O3, pA, 256, 64, 64);
    bn_reduce<<<256,256>>>(pA, 256, 4096);
    bn_apply_split<<<1024,256>>>(pA, 4, 12);
    conv16<16><<<dim3(8,8,4),256>>>(pAH, pAL, pWH+O4, pWL+O4, pA, 256, 64, 64);
    bn_reduce<<<256,256>>>(pA, 256, 4096);
    bn_apply<<<4096,256>>>(pA, 255, 12);

    head_coarse<<<64,256>>>(cw5, cb5, outC);

    // fine stage
    upsample_kernel<<<768,256>>>(outC);
    pack_fine_split<<<dim3(256,4),256>>>(f0f, f1f);

    conv16<4><<<dim3(32,2,4),256>>>(pAH, pAL, pWH+F1, pWL+F1, pA, 64, 128, 128);
    bn_reduce<<<64,256>>>(pA, 64, 16384);
    bn_apply_split<<<1024,256>>>(pA, 2, 14);
    conv16<4><<<dim3(32,2,4),256>>>(pAH, pAL, pWH+F2, pWL+F2, pA, 64, 128, 128);
    bn_reduce<<<64,256>>>(pA, 64, 16384);
    bn_apply_split<<<1024,256>>>(pA, 2, 14);
    conv16<4><<<dim3(32,2,4),256>>>(pAH, pAL, pWH+F3, pWL+F3, pA, 64, 128, 128);
    bn_reduce<<<64,256>>>(pA, 64, 16384);
    bn_apply_split<<<1024,256>>>(pA, 2, 14);
    conv16<4><<<dim3(32,2,4),256>>>(pAH, pAL, pWH+F4, pWL+F4, pA, 64, 128, 128);
    bn_reduce<<<64,256>>>(pA, 64, 16384);
    bn_apply<<<4096,256>>>(pA, 63, 14);

    head_fine<<<256,256>>>(fw5, fb5, outF);
}